// round 8
// baseline (speedup 1.0000x reference)
#include <cuda_runtime.h>
#include <cuda_bf16.h>
#include <cstdint>

#define N_NODES 100000
#define N_EDGES 1600000
#define SCAN_BS 1024
#define SCAN_NB ((N_NODES + SCAN_BS - 1) / SCAN_BS)   // 98

// Ping-pong node-feature buffers (max D=64): 25.6 MB each.
__device__ float g_bufA[(size_t)N_NODES * 64];
__device__ float g_bufB[(size_t)N_NODES * 64];

// CSR scratch (graph identical across all 4 SpMMs -> build once per launch).
__device__ int    g_deg[N_NODES];
__device__ int    g_rowstart[N_NODES + 1];
__device__ int    g_cursor[N_NODES];
__device__ int    g_bsums[128];
__device__ float2 g_epack[N_EDGES];   // {.x = __int_as_float(col), .y = 0.5f*val}

__device__ __forceinline__ float* sel_buf(int s) {
    return (s == 0) ? g_bufA : g_bufB;
}

// ---------------------------------------------------------------------------
// CSR build
// ---------------------------------------------------------------------------
__global__ void zero_deg_kernel() {
    int i = blockIdx.x * blockDim.x + threadIdx.x;
    if (i < N_NODES) g_deg[i] = 0;
}

__global__ void hist_kernel(const int* __restrict__ erow) {
    int i = blockIdx.x * blockDim.x + threadIdx.x;
    if (i < N_EDGES) atomicAdd(&g_deg[erow[i]], 1);
}

// Shfl-based block scan (1024 threads): 2 barriers instead of 10 rounds.
__global__ void scan_local_kernel() {
    __shared__ int ws[32];
    int tid = threadIdx.x, lane = tid & 31, warp = tid >> 5;
    int idx = blockIdx.x * SCAN_BS + tid;
    int v = (idx < N_NODES) ? g_deg[idx] : 0;

    int x = v;  // warp inclusive scan
#pragma unroll
    for (int off = 1; off < 32; off <<= 1) {
        int t = __shfl_up_sync(0xFFFFFFFFu, x, off);
        if (lane >= off) x += t;
    }
    if (lane == 31) ws[warp] = x;
    __syncthreads();
    if (warp == 0) {
        int s = ws[lane];
#pragma unroll
        for (int off = 1; off < 32; off <<= 1) {
            int t = __shfl_up_sync(0xFFFFFFFFu, s, off);
            if (lane >= off) s += t;
        }
        ws[lane] = s;   // inclusive warp totals
    }
    __syncthreads();
    int base = warp ? ws[warp - 1] : 0;
    if (idx < N_NODES) g_rowstart[idx] = base + x - v;   // exclusive
    if (tid == SCAN_BS - 1) g_bsums[blockIdx.x] = base + x;
}

// Every block redundantly scans the 98 block sums (shfl), applies prefix,
// and initializes the scatter cursors. 256 threads.
__global__ void scan_add_kernel() {
    __shared__ int sb[128];
    __shared__ int ws[4];
    int tid = threadIdx.x, lane = tid & 31, warp = tid >> 5;

    int x = 0;
    if (tid < 128) {
        x = (tid < SCAN_NB) ? g_bsums[tid] : 0;
#pragma unroll
        for (int off = 1; off < 32; off <<= 1) {
            int t = __shfl_up_sync(0xFFFFFFFFu, x, off);
            if (lane >= off) x += t;
        }
        if (lane == 31) ws[warp] = x;
    }
    __syncthreads();
    if (tid < 128) {
        int base = 0;
#pragma unroll
        for (int w = 0; w < 4; w++) base += (w < warp) ? ws[w] : 0;
        sb[tid] = base + x;   // inclusive
    }
    __syncthreads();

    int idx = blockIdx.x * blockDim.x + tid;
    if (idx < N_NODES) {
        int blk = idx >> 10;
        int add = (blk == 0) ? 0 : sb[blk - 1];
        int r = g_rowstart[idx] + add;
        g_rowstart[idx] = r;
        g_cursor[idx] = r;
    }
    if (idx == 0) g_rowstart[N_NODES] = N_EDGES;
}

__global__ void scatter_edges_kernel(const int* __restrict__ erow,
                                     const int* __restrict__ ecol,
                                     const float* __restrict__ eval) {
    int i = blockIdx.x * blockDim.x + threadIdx.x;
    if (i >= N_EDGES) return;
    int r = erow[i];
    int p = atomicAdd(&g_cursor[r], 1);
    float2 pk;
    pk.x = __int_as_float(ecol[i]);
    pk.y = 0.5f * eval[i];
    g_epack[p] = pk;
}

// ---------------------------------------------------------------------------
// Warp-level row reduce over a 32-float column slice.
//   C=8 f4-chunks per slice, SUBS=4 edge-parallel lanes.
//   RS = source row stride in float4s; off = f4 offset of this slice.
// Returns reduced chunk in lanes with sub==0. Unrolled x2 for MLP.
// ---------------------------------------------------------------------------
template <int RS>
__device__ __forceinline__ float4 row_reduce32(const float4* __restrict__ src,
                                               int row, int sub, int c, int off) {
    constexpr int SUBS = 4;
    int start = g_rowstart[row];
    int end   = g_rowstart[row + 1];

    float4 a0 = make_float4(0.f, 0.f, 0.f, 0.f);
    float4 a1 = make_float4(0.f, 0.f, 0.f, 0.f);
    int e = start + sub;
    for (; e + SUBS < end; e += 2 * SUBS) {
        float2 ev0 = __ldg(&g_epack[e]);
        float2 ev1 = __ldg(&g_epack[e + SUBS]);
        float4 g0 = __ldg(&src[(size_t)__float_as_int(ev0.x) * RS + off + c]);
        float4 g1 = __ldg(&src[(size_t)__float_as_int(ev1.x) * RS + off + c]);
        float v0 = ev0.y, v1 = ev1.y;
        a0.x = fmaf(v0, g0.x, a0.x);  a0.y = fmaf(v0, g0.y, a0.y);
        a0.z = fmaf(v0, g0.z, a0.z);  a0.w = fmaf(v0, g0.w, a0.w);
        a1.x = fmaf(v1, g1.x, a1.x);  a1.y = fmaf(v1, g1.y, a1.y);
        a1.z = fmaf(v1, g1.z, a1.z);  a1.w = fmaf(v1, g1.w, a1.w);
    }
    if (e < end) {
        float2 ev = __ldg(&g_epack[e]);
        float4 g = __ldg(&src[(size_t)__float_as_int(ev.x) * RS + off + c]);
        float v = ev.y;
        a0.x = fmaf(v, g.x, a0.x);  a0.y = fmaf(v, g.y, a0.y);
        a0.z = fmaf(v, g.z, a0.z);  a0.w = fmaf(v, g.w, a0.w);
    }
    a0.x += a1.x; a0.y += a1.y; a0.z += a1.z; a0.w += a1.w;

#pragma unroll
    for (int off2 = 8; off2 < 32; off2 <<= 1) {
        a0.x += __shfl_xor_sync(0xFFFFFFFFu, a0.x, off2);
        a0.y += __shfl_xor_sync(0xFFFFFFFFu, a0.y, off2);
        a0.z += __shfl_xor_sync(0xFFFFFFFFu, a0.z, off2);
        a0.w += __shfl_xor_sync(0xFFFFFFFFu, a0.w, off2);
    }
    return a0;
}

// ---------------------------------------------------------------------------
// Plain SpMM D=32: one warp per destination row.
// ---------------------------------------------------------------------------
__global__ void spmm_gather32_kernel(const float* __restrict__ ext_src,
                                     int dst_sel) {
    const float4* __restrict__ src = reinterpret_cast<const float4*>(ext_src);
    float4* dst = reinterpret_cast<float4*>(sel_buf(dst_sel));

    int warp_id = (blockIdx.x * blockDim.x + threadIdx.x) >> 5;
    if (warp_id >= N_NODES) return;
    int lane = threadIdx.x & 31;
    int sub = lane >> 3, c = lane & 7;

    float4 acc = row_reduce32<8>(src, warp_id, sub, c, 0);
    if (sub == 0) dst[(size_t)warp_id * 8 + c] = acc;
}

// ---------------------------------------------------------------------------
// Plain SpMM D=64, split: one warp per (row, half). 2x edge parallelism.
// ---------------------------------------------------------------------------
__global__ void spmm_gather64_split_kernel(int src_sel, int dst_sel) {
    const float4* __restrict__ src =
        reinterpret_cast<const float4*>(sel_buf(src_sel));
    float4* dst = reinterpret_cast<float4*>(sel_buf(dst_sel));

    int gwarp = (blockIdx.x * blockDim.x + threadIdx.x) >> 5;
    if (gwarp >= 2 * N_NODES) return;
    int row = gwarp >> 1, half = gwarp & 1;
    int lane = threadIdx.x & 31;
    int sub = lane >> 3, c = lane & 7;

    float4 acc = row_reduce32<16>(src, row, sub, c, half * 8);
    if (sub == 0) dst[(size_t)row * 16 + half * 8 + c] = acc;
}

// ---------------------------------------------------------------------------
// Fused SpMM(D=32) + linear(32->64) + relu. 1024 threads = 32 rows/block.
// ---------------------------------------------------------------------------
__global__ __launch_bounds__(1024)
void spmm_linear32_kernel(const float* __restrict__ Wsrc, int src_sel,
                          int dst_sel, const float* __restrict__ b) {
    __shared__ __align__(16) float sW[32][64];
    __shared__ __align__(16) float sbias[64];
    __shared__ __align__(16) float srow[32][32];

    const float4* __restrict__ src =
        reinterpret_cast<const float4*>(sel_buf(src_sel));
    float2* dst = reinterpret_cast<float2*>(sel_buf(dst_sel));

    int tid = threadIdx.x;
    for (int k = tid; k < 32 * 64; k += 1024) sW[k >> 6][k & 63] = Wsrc[k];
    if (tid < 64) sbias[tid] = b[tid];

    int warp = tid >> 5, lane = tid & 31;
    int row = blockIdx.x * 32 + warp;   // 100000 = 3125 * 32, exact
    int sub = lane >> 3, c = lane & 7;

    float4 acc = row_reduce32<8>(src, row, sub, c, 0);
    if (sub == 0) reinterpret_cast<float4*>(srow[warp])[c] = acc;
    __syncthreads();

    // Each lane computes outputs (2*lane, 2*lane+1).
    const float2* sW2 = reinterpret_cast<const float2*>(&sW[0][0]);
    float2 o = reinterpret_cast<const float2*>(sbias)[lane];
#pragma unroll
    for (int k = 0; k < 32; k++) {
        float r = srow[warp][k];
        float2 w = sW2[k * 32 + lane];
        o.x = fmaf(r, w.x, o.x);
        o.y = fmaf(r, w.y, o.y);
    }
    o.x = fmaxf(o.x, 0.f);
    o.y = fmaxf(o.y, 0.f);
    dst[(size_t)row * 32 + lane] = o;
}

// ---------------------------------------------------------------------------
// Fused SpMM(D=64, split) + linear(64->64). 1024 threads = 16 rows/block
// (2 warps per row in the reduce; warp (2r+half) computes output half).
// ---------------------------------------------------------------------------
__global__ __launch_bounds__(1024)
void spmm_linear64_kernel(int src_sel, float* __restrict__ ext_dst,
                          const float* __restrict__ Wsrc,
                          const float* __restrict__ b) {
    __shared__ __align__(16) float sW[64][64];
    __shared__ __align__(16) float sbias[64];
    __shared__ __align__(16) float srow[16][64];

    const float4* __restrict__ src =
        reinterpret_cast<const float4*>(sel_buf(src_sel));

    int tid = threadIdx.x;
    for (int k = tid; k < 64 * 64; k += 1024) sW[k >> 6][k & 63] = Wsrc[k];
    if (tid < 64) sbias[tid] = b[tid];

    int warp = tid >> 5, lane = tid & 31;
    int r = warp >> 1, half = warp & 1;
    int row = blockIdx.x * 16 + r;      // 100000 = 6250 * 16, exact
    int sub = lane >> 3, c = lane & 7;

    float4 acc = row_reduce32<16>(src, row, sub, c, half * 8);
    if (sub == 0) reinterpret_cast<float4*>(srow[r])[half * 8 + c] = acc;
    __syncthreads();

    // Warp (2r+half) computes outputs j = half*32 + lane for row r.
    int j = half * 32 + lane;
    float o = sbias[j];
#pragma unroll
    for (int k = 0; k < 64; k++) {
        o = fmaf(srow[r][k], sW[k][j], o);
    }
    ext_dst[(size_t)row * 64 + j] = o;
}

// ---------------------------------------------------------------------------
// Launch sequence:
//   CSR build (5 kernels, shared by all 4 propagations)
//   bufA <- spmm(x)                          (D=32)
//   bufB <- relu(spmm(bufA) @ W1 + b1)       (fused, 32 -> 64)
//   bufA <- spmm(bufB)                       (D=64, 2-warp split)
//   out  <- spmm(bufA) @ W2 + b2             (fused, 64 -> 64, split)
// ---------------------------------------------------------------------------
extern "C" void kernel_launch(void* const* d_in, const int* in_sizes, int n_in,
                              void* d_out, int out_size) {
    const float* x    = (const float*)d_in[0];
    const float* evl  = (const float*)d_in[1];
    const int*   erow = (const int*)  d_in[2];
    const int*   ecol = (const int*)  d_in[3];
    const float* W1   = (const float*)d_in[4];
    const float* b1   = (const float*)d_in[5];
    const float* W2   = (const float*)d_in[6];
    const float* b2   = (const float*)d_in[7];
    float* out = (float*)d_out;

    const int TPB = 256;
    int node_blocks = (N_NODES + TPB - 1) / TPB;
    int edge_blocks = (N_EDGES + TPB - 1) / TPB;

    // --- CSR build ---
    zero_deg_kernel<<<node_blocks, TPB>>>();
    hist_kernel<<<edge_blocks, TPB>>>(erow);
    scan_local_kernel<<<SCAN_NB, SCAN_BS>>>();
    scan_add_kernel<<<node_blocks, TPB>>>();
    scatter_edges_kernel<<<edge_blocks, TPB>>>(erow, ecol, evl);

    // --- layer 1 ---
    spmm_gather32_kernel<<<(N_NODES * 32) / TPB + 1, TPB>>>(x, 0);
    spmm_linear32_kernel<<<N_NODES / 32, 1024>>>(W1, 0, 1, b1);

    // --- layer 2 ---
    spmm_gather64_split_kernel<<<(2 * N_NODES * 32) / TPB, TPB>>>(1, 0);
    spmm_linear64_kernel<<<N_NODES / 16, 1024>>>(0, out, W2, b2);
}

// round 12
// speedup vs baseline: 1.3420x; 1.3420x over previous
#include <cuda_runtime.h>
#include <cuda_fp16.h>
#include <cstdint>

#define N_NODES 100000
#define N_EDGES 1600000
#define SCAN_BS 1024
#define SCAN_NB ((N_NODES + SCAN_BS - 1) / SCAN_BS)   // 98

// Ping-pong node-feature buffers. bufA holds f32 D=32 (layer1) then f16 D=64
// (layer2 intermediate); bufB holds f16 D=64 (post-relu layer1 output).
__device__ float g_bufA[(size_t)N_NODES * 64];
__device__ float g_bufB[(size_t)N_NODES * 64];

// CSR scratch (graph identical across all 4 SpMMs -> build once per launch).
__device__ int    g_deg[N_NODES];
__device__ int    g_rowstart[N_NODES + 1];
__device__ int    g_cursor[N_NODES];
__device__ int    g_bsums[128];
__device__ float2 g_epack[N_EDGES];   // {.x = __int_as_float(col), .y = 0.5f*val}

// ---------------------------------------------------------------------------
// CSR build
// ---------------------------------------------------------------------------
__global__ void zero_deg_kernel() {
    int i = blockIdx.x * blockDim.x + threadIdx.x;
    if (i < N_NODES) g_deg[i] = 0;
}

__global__ void hist_kernel(const int* __restrict__ erow) {
    int i = blockIdx.x * blockDim.x + threadIdx.x;
    if (i < N_EDGES) atomicAdd(&g_deg[erow[i]], 1);
}

// Per-block inclusive scan (Hillis-Steele over 1024), write exclusive result.
__global__ void scan_local_kernel() {
    __shared__ int s[SCAN_BS];
    int tid = threadIdx.x;
    int idx = blockIdx.x * SCAN_BS + tid;
    int v = (idx < N_NODES) ? g_deg[idx] : 0;
    s[tid] = v;
    __syncthreads();
#pragma unroll
    for (int off = 1; off < SCAN_BS; off <<= 1) {
        int t = (tid >= off) ? s[tid - off] : 0;
        __syncthreads();
        s[tid] += t;
        __syncthreads();
    }
    if (idx < N_NODES) g_rowstart[idx] = s[tid] - v;   // exclusive
    if (tid == SCAN_BS - 1) g_bsums[blockIdx.x] = s[tid];
}

// Every block redundantly scans the 98 block sums, applies prefix, inits cursors.
__global__ void scan_add_kernel() {
    __shared__ int sb[128];
    int tid = threadIdx.x;   // 256 threads
    if (tid < 128) sb[tid] = (tid < SCAN_NB) ? g_bsums[tid] : 0;
    __syncthreads();
#pragma unroll
    for (int off = 1; off < 128; off <<= 1) {
        int t = (tid < 128 && tid >= off) ? sb[tid - off] : 0;
        __syncthreads();
        if (tid < 128) sb[tid] += t;
        __syncthreads();
    }
    int idx = blockIdx.x * blockDim.x + tid;
    if (idx < N_NODES) {
        int blk = idx >> 10;
        int add = (blk == 0) ? 0 : sb[blk - 1];
        int r = g_rowstart[idx] + add;
        g_rowstart[idx] = r;
        g_cursor[idx] = r;
    }
    if (idx == 0) g_rowstart[N_NODES] = N_EDGES;
}

__global__ void scatter_edges_kernel(const int* __restrict__ erow,
                                     const int* __restrict__ ecol,
                                     const float* __restrict__ eval) {
    int i = blockIdx.x * blockDim.x + threadIdx.x;
    if (i >= N_EDGES) return;
    int r = erow[i];
    int p = atomicAdd(&g_cursor[r], 1);
    float2 pk;
    pk.x = __int_as_float(ecol[i]);
    pk.y = 0.5f * eval[i];
    g_epack[p] = pk;
}

// ---------------------------------------------------------------------------
// f32 warp-level row reduce, D=32: C=8 f4-chunks, SUBS=4 edge lanes, unroll x2.
// Returns reduced chunk in lanes with sub==0.
// ---------------------------------------------------------------------------
__device__ __forceinline__ float4 row_reduce32f(const float4* __restrict__ src,
                                                int row, int sub, int c) {
    constexpr int SUBS = 4;
    int start = g_rowstart[row];
    int end   = g_rowstart[row + 1];

    float4 a0 = make_float4(0.f, 0.f, 0.f, 0.f);
    float4 a1 = make_float4(0.f, 0.f, 0.f, 0.f);
    int e = start + sub;
    for (; e + SUBS < end; e += 2 * SUBS) {
        float2 ev0 = __ldg(&g_epack[e]);
        float2 ev1 = __ldg(&g_epack[e + SUBS]);
        float4 g0 = __ldg(&src[(size_t)__float_as_int(ev0.x) * 8 + c]);
        float4 g1 = __ldg(&src[(size_t)__float_as_int(ev1.x) * 8 + c]);
        float v0 = ev0.y, v1 = ev1.y;
        a0.x = fmaf(v0, g0.x, a0.x);  a0.y = fmaf(v0, g0.y, a0.y);
        a0.z = fmaf(v0, g0.z, a0.z);  a0.w = fmaf(v0, g0.w, a0.w);
        a1.x = fmaf(v1, g1.x, a1.x);  a1.y = fmaf(v1, g1.y, a1.y);
        a1.z = fmaf(v1, g1.z, a1.z);  a1.w = fmaf(v1, g1.w, a1.w);
    }
    if (e < end) {
        float2 ev = __ldg(&g_epack[e]);
        float4 g = __ldg(&src[(size_t)__float_as_int(ev.x) * 8 + c]);
        float v = ev.y;
        a0.x = fmaf(v, g.x, a0.x);  a0.y = fmaf(v, g.y, a0.y);
        a0.z = fmaf(v, g.z, a0.z);  a0.w = fmaf(v, g.w, a0.w);
    }
    a0.x += a1.x; a0.y += a1.y; a0.z += a1.z; a0.w += a1.w;

#pragma unroll
    for (int off = 8; off < 32; off <<= 1) {
        a0.x += __shfl_xor_sync(0xFFFFFFFFu, a0.x, off);
        a0.y += __shfl_xor_sync(0xFFFFFFFFu, a0.y, off);
        a0.z += __shfl_xor_sync(0xFFFFFFFFu, a0.z, off);
        a0.w += __shfl_xor_sync(0xFFFFFFFFu, a0.w, off);
    }
    return a0;
}

// ---------------------------------------------------------------------------
// f16 warp-level row reduce, D=64: each f4 chunk = 8 halfs -> C=8, SUBS=4.
// f32 accumulation in two float4s (cols 8c..8c+3 / 8c+4..8c+7).
// ---------------------------------------------------------------------------
__device__ __forceinline__ void fma8h(float4 g, float v, float4& lo, float4& hi) {
    const __half2* h = reinterpret_cast<const __half2*>(&g);
    float2 p;
    p = __half22float2(h[0]); lo.x = fmaf(v, p.x, lo.x); lo.y = fmaf(v, p.y, lo.y);
    p = __half22float2(h[1]); lo.z = fmaf(v, p.x, lo.z); lo.w = fmaf(v, p.y, lo.w);
    p = __half22float2(h[2]); hi.x = fmaf(v, p.x, hi.x); hi.y = fmaf(v, p.y, hi.y);
    p = __half22float2(h[3]); hi.z = fmaf(v, p.x, hi.z); hi.w = fmaf(v, p.y, hi.w);
}

__device__ __forceinline__ void row_reduce64h(const float4* __restrict__ src,
                                              int row, int sub, int c,
                                              float4& lo_out, float4& hi_out) {
    constexpr int SUBS = 4;
    int start = g_rowstart[row];
    int end   = g_rowstart[row + 1];

    float4 l0 = make_float4(0.f, 0.f, 0.f, 0.f), h0 = l0;
    float4 l1 = l0, h1 = l0;
    int e = start + sub;
    for (; e + SUBS < end; e += 2 * SUBS) {
        float2 ev0 = __ldg(&g_epack[e]);
        float2 ev1 = __ldg(&g_epack[e + SUBS]);
        float4 g0 = __ldg(&src[(size_t)__float_as_int(ev0.x) * 8 + c]);
        float4 g1 = __ldg(&src[(size_t)__float_as_int(ev1.x) * 8 + c]);
        fma8h(g0, ev0.y, l0, h0);
        fma8h(g1, ev1.y, l1, h1);
    }
    if (e < end) {
        float2 ev = __ldg(&g_epack[e]);
        float4 g = __ldg(&src[(size_t)__float_as_int(ev.x) * 8 + c]);
        fma8h(g, ev.y, l0, h0);
    }
    l0.x += l1.x; l0.y += l1.y; l0.z += l1.z; l0.w += l1.w;
    h0.x += h1.x; h0.y += h1.y; h0.z += h1.z; h0.w += h1.w;

#pragma unroll
    for (int off = 8; off < 32; off <<= 1) {
        l0.x += __shfl_xor_sync(0xFFFFFFFFu, l0.x, off);
        l0.y += __shfl_xor_sync(0xFFFFFFFFu, l0.y, off);
        l0.z += __shfl_xor_sync(0xFFFFFFFFu, l0.z, off);
        l0.w += __shfl_xor_sync(0xFFFFFFFFu, l0.w, off);
        h0.x += __shfl_xor_sync(0xFFFFFFFFu, h0.x, off);
        h0.y += __shfl_xor_sync(0xFFFFFFFFu, h0.y, off);
        h0.z += __shfl_xor_sync(0xFFFFFFFFu, h0.z, off);
        h0.w += __shfl_xor_sync(0xFFFFFFFFu, h0.w, off);
    }
    lo_out = l0; hi_out = h0;
}

// ---------------------------------------------------------------------------
// Pass 1: SpMM D=32 f32, x -> bufA. One warp per row.
// ---------------------------------------------------------------------------
__global__ void spmm_gather32_kernel(const float* __restrict__ x) {
    const float4* __restrict__ src = reinterpret_cast<const float4*>(x);
    float4* dst = reinterpret_cast<float4*>(g_bufA);

    int warp_id = (blockIdx.x * blockDim.x + threadIdx.x) >> 5;
    if (warp_id >= N_NODES) return;
    int lane = threadIdx.x & 31;
    int sub = lane >> 3, c = lane & 7;

    float4 acc = row_reduce32f(src, warp_id, sub, c);
    if (sub == 0) dst[(size_t)warp_id * 8 + c] = acc;
}

// ---------------------------------------------------------------------------
// Pass 2: fused SpMM(D=32 f32, bufA) + linear(32->64) + relu -> bufB (f16).
// 256 threads = 8 warps = 8 rows; warp-private srow + __syncwarp.
// ---------------------------------------------------------------------------
__global__ void spmm_linear32_kernel(const float* __restrict__ W,
                                     const float* __restrict__ b) {
    constexpr int WARPS = 8;
    __shared__ __align__(16) float sW[32][64];
    __shared__ __align__(16) float sbias[64];
    __shared__ __align__(16) float srow[WARPS][32];

    const float4* __restrict__ src = reinterpret_cast<const float4*>(g_bufA);
    __half2* dst = reinterpret_cast<__half2*>(g_bufB);

    int tid = threadIdx.x;
    for (int k = tid; k < 32 * 64; k += 256) sW[k >> 6][k & 63] = W[k];
    if (tid < 64) sbias[tid] = b[tid];
    __syncthreads();

    int warp = tid >> 5, lane = tid & 31;
    int row = blockIdx.x * WARPS + warp;   // 100000 = 12500 * 8, exact
    int sub = lane >> 3, c = lane & 7;

    float4 acc = row_reduce32f(src, row, sub, c);
    if (sub == 0) reinterpret_cast<float4*>(srow[warp])[c] = acc;
    __syncwarp();

    const float2* sW2 = reinterpret_cast<const float2*>(&sW[0][0]);
    float2 o = reinterpret_cast<const float2*>(sbias)[lane];
#pragma unroll
    for (int k = 0; k < 32; k++) {
        float r = srow[warp][k];
        float2 w = sW2[k * 32 + lane];
        o.x = fmaf(r, w.x, o.x);
        o.y = fmaf(r, w.y, o.y);
    }
    o.x = fmaxf(o.x, 0.f);
    o.y = fmaxf(o.y, 0.f);
    dst[(size_t)row * 32 + lane] = __floats2half2_rn(o.x, o.y);
}

// ---------------------------------------------------------------------------
// Pass 3: SpMM D=64 f16, bufB -> bufA (f16). One warp per row, SUBS=4.
// ---------------------------------------------------------------------------
__global__ void spmm_gather64h_kernel() {
    const float4* __restrict__ src = reinterpret_cast<const float4*>(g_bufB);
    float4* dst = reinterpret_cast<float4*>(g_bufA);

    int warp_id = (blockIdx.x * blockDim.x + threadIdx.x) >> 5;
    if (warp_id >= N_NODES) return;
    int lane = threadIdx.x & 31;
    int sub = lane >> 3, c = lane & 7;

    float4 lo, hi;
    row_reduce64h(src, warp_id, sub, c, lo, hi);
    if (sub == 0) {
        float4 pk;
        __half2* p = reinterpret_cast<__half2*>(&pk);
        p[0] = __floats2half2_rn(lo.x, lo.y);
        p[1] = __floats2half2_rn(lo.z, lo.w);
        p[2] = __floats2half2_rn(hi.x, hi.y);
        p[3] = __floats2half2_rn(hi.z, hi.w);
        dst[(size_t)warp_id * 8 + c] = pk;
    }
}

// ---------------------------------------------------------------------------
// Pass 4: fused SpMM(D=64 f16, bufA) + linear(64->64) + bias -> out (f32).
// 256 threads = 8 warps = 8 rows; warp-private srow + __syncwarp.
// ---------------------------------------------------------------------------
__global__ void spmm_linear64h_kernel(float* __restrict__ out,
                                      const float* __restrict__ W,
                                      const float* __restrict__ b) {
    constexpr int WARPS = 8;
    __shared__ __align__(16) float sW[64][64];
    __shared__ __align__(16) float sbias[64];
    __shared__ __align__(16) float srow[WARPS][64];

    const float4* __restrict__ src = reinterpret_cast<const float4*>(g_bufA);

    int tid = threadIdx.x;
    for (int k = tid; k < 64 * 64; k += 256) sW[k >> 6][k & 63] = W[k];
    if (tid < 64) sbias[tid] = b[tid];
    __syncthreads();

    int warp = tid >> 5, lane = tid & 31;
    int row = blockIdx.x * WARPS + warp;   // exact
    int sub = lane >> 3, c = lane & 7;

    float4 lo, hi;
    row_reduce64h(src, row, sub, c, lo, hi);
    if (sub == 0) {
        float4* s4 = reinterpret_cast<float4*>(srow[warp]);
        s4[2 * c]     = lo;   // cols 8c .. 8c+3
        s4[2 * c + 1] = hi;   // cols 8c+4 .. 8c+7
    }
    __syncwarp();

    const float2* sW2 = reinterpret_cast<const float2*>(&sW[0][0]);
    float2 o = reinterpret_cast<const float2*>(sbias)[lane];
#pragma unroll
    for (int k = 0; k < 64; k++) {
        float r = srow[warp][k];
        float2 w = sW2[k * 32 + lane];
        o.x = fmaf(r, w.x, o.x);
        o.y = fmaf(r, w.y, o.y);
    }
    reinterpret_cast<float2*>(out)[(size_t)row * 32 + lane] = o;
}

// ---------------------------------------------------------------------------
// Launch sequence:
//   CSR build (5 kernels, shared by all 4 propagations)
//   bufA(f32,32) <- spmm(x)
//   bufB(f16,64) <- relu(spmm(bufA) @ W1 + b1)     (fused)
//   bufA(f16,64) <- spmm(bufB)
//   out(f32)     <- spmm(bufA) @ W2 + b2           (fused)
// ---------------------------------------------------------------------------
extern "C" void kernel_launch(void* const* d_in, const int* in_sizes, int n_in,
                              void* d_out, int out_size) {
    const float* x    = (const float*)d_in[0];
    const float* evl  = (const float*)d_in[1];
    const int*   erow = (const int*)  d_in[2];
    const int*   ecol = (const int*)  d_in[3];
    const float* W1   = (const float*)d_in[4];
    const float* b1   = (const float*)d_in[5];
    const float* W2   = (const float*)d_in[6];
    const float* b2   = (const float*)d_in[7];
    float* out = (float*)d_out;

    const int TPB = 256;
    int node_blocks = (N_NODES + TPB - 1) / TPB;
    int edge_blocks = (N_EDGES + TPB - 1) / TPB;
    int warp_blocks = (N_NODES * 32 + TPB - 1) / TPB;   // 12500
    int fused_blocks = N_NODES / 8;                      // 12500

    // --- CSR build ---
    zero_deg_kernel<<<node_blocks, TPB>>>();
    hist_kernel<<<edge_blocks, TPB>>>(erow);
    scan_local_kernel<<<SCAN_NB, SCAN_BS>>>();
    scan_add_kernel<<<node_blocks, TPB>>>();
    scatter_edges_kernel<<<edge_blocks, TPB>>>(erow, ecol, evl);

    // --- layer 1 ---
    spmm_gather32_kernel<<<warp_blocks, TPB>>>(x);
    spmm_linear32_kernel<<<fused_blocks, TPB>>>(W1, b1);

    // --- layer 2 (f16 features) ---
    spmm_gather64h_kernel<<<warp_blocks, TPB>>>();
    spmm_linear64h_kernel<<<fused_blocks, TPB>>>(out, W2, b2);
}